// round 13
// baseline (speedup 1.0000x reference)
#include <cuda_runtime.h>
#include <cuda_bf16.h>
#include <math.h>
#include <stdint.h>

#define NN   50000
#define EE   800000
#define EH   400000   // EE/2
#define INF  64
#define OUTF 64
#define KH   256      // HID*IN
#define KTOT 320      // KH + IN
#define NKC  20       // K chunks of 16
#define NPART 196     // ceil(NN/256)

// ---------------------------------------------------------------------------
// Scratch (__device__ globals)
// ---------------------------------------------------------------------------
__device__ float  g_neigh[(size_t)NN * KH];   // [n][k], mean-scaled
__device__ int    g_deg[NN];
__device__ int    g_rowstart[NN + 1];
__device__ int    g_cursor[NN];
__device__ int    g_part[256];
__device__ float4 g_ws[EE];                   // {wsx, wsy, wsz, bitcast(src)}
__device__ uint4  g_Wfrag[NKC * 8 * 32];      // prepacked B frags {Bh0,Bh1,Bl0,Bl1}
__device__ float  g_bsum[OUTF];               // b_neigh + bias

// ---------------------------------------------------------------------------
// helpers
// ---------------------------------------------------------------------------
#define MMA_BF16(d, a0, a1, a2, a3, b0, b1)                                   \
    asm volatile("mma.sync.aligned.m16n8k16.row.col.f32.bf16.bf16.f32 "       \
                 "{%0,%1,%2,%3}, {%4,%5,%6,%7}, {%8,%9}, {%0,%1,%2,%3};"      \
                 : "+f"((d)[0]), "+f"((d)[1]), "+f"((d)[2]), "+f"((d)[3])     \
                 : "r"(a0), "r"(a1), "r"(a2), "r"(a3), "r"(b0), "r"(b1))

__device__ __forceinline__ uint32_t pk_hi(float2 v, float2& res) {
    __nv_bfloat162 h = __float22bfloat162_rn(v);
    float2 hf = __bfloat1622float2(h);
    res = make_float2(v.x - hf.x, v.y - hf.y);
    return *reinterpret_cast<uint32_t*>(&h);
}
__device__ __forceinline__ uint32_t pk(float2 v) {
    __nv_bfloat162 h = __float22bfloat162_rn(v);
    return *reinterpret_cast<uint32_t*>(&h);
}

// ---------------------------------------------------------------------------
// 1) Degree histogram
// ---------------------------------------------------------------------------
__global__ void hist_kernel(const int* __restrict__ dst)
{
    int e = blockIdx.x * blockDim.x + threadIdx.x;
    if (e < EE) atomicAdd(&g_deg[__ldg(&dst[e])], 1);
}

// ---------------------------------------------------------------------------
// 2a) Per-block degree partial sums (R11 scheme)
// ---------------------------------------------------------------------------
__global__ void part_kernel()
{
    __shared__ int s[256];
    const int t = threadIdx.x;
    const int idx = blockIdx.x * 256 + t;
    s[t] = (idx < NN) ? g_deg[idx] : 0;
    __syncthreads();
#pragma unroll
    for (int off = 128; off > 0; off >>= 1) {
        if (t < off) s[t] += s[t + off];
        __syncthreads();
    }
    if (t == 0) g_part[blockIdx.x] = s[0];
}

// ---------------------------------------------------------------------------
// 2b) rowstart: each block self-scans the 196 partials, then its 256 degrees
// ---------------------------------------------------------------------------
__global__ void rowstart_kernel()
{
    __shared__ int sp[256];
    __shared__ int s[256];
    const int t = threadIdx.x;

    sp[t] = (t < NPART) ? g_part[t] : 0;
    const int idx = blockIdx.x * 256 + t;
    const int v = (idx < NN) ? g_deg[idx] : 0;
    s[t] = v;
    __syncthreads();
    for (int off = 1; off < 256; off <<= 1) {
        int xp = (t >= off) ? sp[t - off] : 0;
        int x  = (t >= off) ? s[t - off]  : 0;
        __syncthreads();
        sp[t] += xp;
        s[t]  += x;
        __syncthreads();
    }
    const int poff = (blockIdx.x > 0) ? sp[blockIdx.x - 1] : 0;
    const int excl = s[t] - v + poff;
    if (idx < NN) {
        g_rowstart[idx] = excl;
        g_cursor[idx]   = excl;
    }
    if (idx == NN - 1) g_rowstart[NN] = EE;
}

// ---------------------------------------------------------------------------
// 3) Scatter: 2 edges per thread
// ---------------------------------------------------------------------------
__global__ void __launch_bounds__(256) scatter_kernel(
    const float* __restrict__ pos,
    const int*   __restrict__ src,
    const int*   __restrict__ dst)
{
    const int base = blockIdx.x * blockDim.x + threadIdx.x;
    if (base >= EH) return;
#pragma unroll
    for (int h = 0; h < 2; h++) {
        const int e = base + h * EH;
        const int s = __ldg(&src[e]);
        const int d = __ldg(&dst[e]);

        const float rx = __ldg(&pos[d * 3 + 0]) - __ldg(&pos[s * 3 + 0]);
        const float ry = __ldg(&pos[d * 3 + 1]) - __ldg(&pos[s * 3 + 1]);
        const float rz = __ldg(&pos[d * 3 + 2]) - __ldg(&pos[s * 3 + 2]);
        const float scal = sqrtf(fmaf(rx, rx, fmaf(ry, ry, rz * rz))) + 1e-7f;
        const float inv  = __fdividef(1.0f, scal);

        const int p = atomicAdd(&g_cursor[d], 1);
        g_ws[p] = make_float4((rx + 1.0f) * inv, (ry + 1.0f) * inv,
                              (rz + 1.0f) * inv, __int_as_float(s));
    }
}

// ---------------------------------------------------------------------------
// 4) Aggregate: two warps per node; lane owns 4 channels. FOUR-edge unroll:
//    4 independent ws loads + 4 independent feat gathers per iteration,
//    dual accumulator banks. (4-channel layout keeps regs ~55.)
// ---------------------------------------------------------------------------
__global__ void __launch_bounds__(256) aggregate_kernel(
    const float* __restrict__ feat,
    const float* __restrict__ W_sp,
    const float* __restrict__ b_sp)
{
    const int lane = threadIdx.x & 31;
    const int gw   = (blockIdx.x * blockDim.x + threadIdx.x) >> 5;
    const int node = gw >> 1;
    const int half = gw & 1;
    if (node >= NN) return;

    const int k0 = half * 128 + lane * 4;   // 4 channels, same `in`
    const int in = half * 32 + lane;
    const float* __restrict__ fp = feat + in;

    float w0[4], w1[4], w2[4], bb[4];
#pragma unroll
    for (int i = 0; i < 4; i++) {
        const int k = k0 + i;
        w0[i] = __ldg(&W_sp[k * 3 + 0]);
        w1[i] = __ldg(&W_sp[k * 3 + 1]);
        w2[i] = __ldg(&W_sp[k * 3 + 2]);
        bb[i] = __ldg(&b_sp[k]);
    }

    const int start = g_rowstart[node];
    const int end   = g_rowstart[node + 1];

    float acc[4], acc2[4];
#pragma unroll
    for (int i = 0; i < 4; i++) { acc[i] = 0.0f; acc2[i] = 0.0f; }

    int j = start;
    for (; j + 4 <= end; j += 4) {
        const float4 wa = __ldg(&g_ws[j]);
        const float4 wb = __ldg(&g_ws[j + 1]);
        const float4 wc = __ldg(&g_ws[j + 2]);
        const float4 wd = __ldg(&g_ws[j + 3]);
        const float fa = __ldg(fp + ((size_t)__float_as_int(wa.w) << 6));
        const float fb = __ldg(fp + ((size_t)__float_as_int(wb.w) << 6));
        const float fc = __ldg(fp + ((size_t)__float_as_int(wc.w) << 6));
        const float fd = __ldg(fp + ((size_t)__float_as_int(wd.w) << 6));
#pragma unroll
        for (int i = 0; i < 4; i++) {
            float ta = fmaf(wa.x, w0[i], fmaf(wa.y, w1[i], fmaf(wa.z, w2[i], bb[i])));
            float tb = fmaf(wb.x, w0[i], fmaf(wb.y, w1[i], fmaf(wb.z, w2[i], bb[i])));
            float tc = fmaf(wc.x, w0[i], fmaf(wc.y, w1[i], fmaf(wc.z, w2[i], bb[i])));
            float td = fmaf(wd.x, w0[i], fmaf(wd.y, w1[i], fmaf(wd.z, w2[i], bb[i])));
            ta = fmaxf(ta, 0.01f * ta);
            tb = fmaxf(tb, 0.01f * tb);
            tc = fmaxf(tc, 0.01f * tc);
            td = fmaxf(td, 0.01f * td);
            acc[i]  = fmaf(ta, fa, acc[i]);
            acc2[i] = fmaf(tb, fb, acc2[i]);
            acc[i]  = fmaf(tc, fc, acc[i]);
            acc2[i] = fmaf(td, fd, acc2[i]);
        }
    }
    for (; j < end; j++) {
        const float4 wa = __ldg(&g_ws[j]);
        const float fa = __ldg(fp + ((size_t)__float_as_int(wa.w) << 6));
#pragma unroll
        for (int i = 0; i < 4; i++) {
            float ta = fmaf(wa.x, w0[i], fmaf(wa.y, w1[i], fmaf(wa.z, w2[i], bb[i])));
            ta = fmaxf(ta, 0.01f * ta);
            acc[i] = fmaf(ta, fa, acc[i]);
        }
    }

    const float sc = (end > start) ? __fdividef(1.0f, (float)(end - start)) : 0.0f;
    *reinterpret_cast<float4*>(&g_neigh[(size_t)node * KH + k0]) =
        make_float4((acc[0] + acc2[0]) * sc, (acc[1] + acc2[1]) * sc,
                    (acc[2] + acc2[2]) * sc, (acc[3] + acc2[3]) * sc);
}

// ---------------------------------------------------------------------------
// 5) Weight prep
// ---------------------------------------------------------------------------
__global__ void wprep_kernel(const float* __restrict__ W_self,
                             const float* __restrict__ W_neigh,
                             const float* __restrict__ b_neigh,
                             const float* __restrict__ bias)
{
    int idx = blockIdx.x * blockDim.x + threadIdx.x;
    if (idx < OUTF) g_bsum[idx] = __ldg(&b_neigh[idx]) + __ldg(&bias[idx]);
    if (idx >= NKC * 8 * 32) return;

    const int lane = idx & 31;
    const int nc   = (idx >> 5) & 7;
    const int kc   = idx >> 8;
    const int n    = nc * 8 + (lane >> 2);
    const int k0   = kc * 16 + (lane & 3) * 2;

    float v[4];
#pragma unroll
    for (int r = 0; r < 2; r++)
#pragma unroll
        for (int j = 0; j < 2; j++) {
            const int k = k0 + r * 8 + j;
            v[r * 2 + j] = (k < KH) ? __ldg(&W_neigh[(size_t)n * KH + k])
                                    : __ldg(&W_self[(size_t)n * INF + (k - KH)]);
        }

    float2 r0, r1;
    uint4 q;
    q.x = pk_hi(make_float2(v[0], v[1]), r0);
    q.y = pk_hi(make_float2(v[2], v[3]), r1);
    q.z = pk(r0);
    q.w = pk(r1);
    g_Wfrag[idx] = q;
}

// ---------------------------------------------------------------------------
// 6) Node GEMM via mma.sync bf16 (3-term hi/lo split), A from f32 gmem.
// ---------------------------------------------------------------------------
__global__ void __launch_bounds__(256) gemm_kernel(
    const float* __restrict__ feat, float* __restrict__ out)
{
    const int lane = threadIdx.x & 31;
    const int warp = threadIdx.x >> 5;
    const int m    = blockIdx.x * 128 + warp * 16 + (lane >> 2);
    const int kq   = (lane & 3) * 2;

    const bool v0 = (m < NN);
    const bool v1 = (m + 8 < NN);
    const float2 z2 = make_float2(0.f, 0.f);

    float D[8][4];
#pragma unroll
    for (int nc = 0; nc < 8; nc++)
#pragma unroll
        for (int i = 0; i < 4; i++) D[nc][i] = 0.0f;

#pragma unroll 4
    for (int kc = 0; kc < NKC; kc++) {
        float2 p00, p10, p01, p11;
        if (kc < 16) {
            const int c = kc * 16 + kq;
            const float* r0 = &g_neigh[(size_t)m * KH + c];
            const float* r1 = &g_neigh[(size_t)(m + 8) * KH + c];
            p00 = v0 ? __ldg(reinterpret_cast<const float2*>(r0))     : z2;
            p01 = v0 ? __ldg(reinterpret_cast<const float2*>(r0 + 8)) : z2;
            p10 = v1 ? __ldg(reinterpret_cast<const float2*>(r1))     : z2;
            p11 = v1 ? __ldg(reinterpret_cast<const float2*>(r1 + 8)) : z2;
        } else {
            const int c = (kc - 16) * 16 + kq;
            const float* r0 = &feat[(size_t)m * INF + c];
            const float* r1 = &feat[(size_t)(m + 8) * INF + c];
            p00 = v0 ? __ldg(reinterpret_cast<const float2*>(r0))     : z2;
            p01 = v0 ? __ldg(reinterpret_cast<const float2*>(r0 + 8)) : z2;
            p10 = v1 ? __ldg(reinterpret_cast<const float2*>(r1))     : z2;
            p11 = v1 ? __ldg(reinterpret_cast<const float2*>(r1 + 8)) : z2;
        }
        float2 q00, q10, q01, q11;
        const uint32_t ah0 = pk_hi(p00, q00);
        const uint32_t ah1 = pk_hi(p10, q10);
        const uint32_t ah2 = pk_hi(p01, q01);
        const uint32_t ah3 = pk_hi(p11, q11);
        const uint32_t al0 = pk(q00), al1 = pk(q10), al2 = pk(q01), al3 = pk(q11);

        const uint4* wf = &g_Wfrag[(kc * 8) * 32 + lane];
#pragma unroll
        for (int nc = 0; nc < 8; nc++) {
            const uint4 b = __ldg(wf + nc * 32);
            MMA_BF16(D[nc], ah0, ah1, ah2, ah3, b.x, b.y);   // Ah * Wh
            MMA_BF16(D[nc], al0, al1, al2, al3, b.x, b.y);   // Al * Wh
            MMA_BF16(D[nc], ah0, ah1, ah2, ah3, b.z, b.w);   // Ah * Wl
        }
    }

#pragma unroll
    for (int nc = 0; nc < 8; nc++) {
        const int n = nc * 8 + kq;
        const float bx = __ldg(&g_bsum[n]);
        const float by = __ldg(&g_bsum[n + 1]);
        if (v0)
            *reinterpret_cast<float2*>(&out[(size_t)m * OUTF + n]) =
                make_float2(D[nc][0] + bx, D[nc][1] + by);
        if (v1)
            *reinterpret_cast<float2*>(&out[(size_t)(m + 8) * OUTF + n]) =
                make_float2(D[nc][2] + bx, D[nc][3] + by);
    }
}

// ---------------------------------------------------------------------------
// Launch
// ---------------------------------------------------------------------------
extern "C" void kernel_launch(void* const* d_in, const int* in_sizes, int n_in,
                              void* d_out, int out_size)
{
    const float* feat    = (const float*)d_in[0];
    const float* pos     = (const float*)d_in[1];
    const int*   src     = (const int*)  d_in[2];
    const int*   dst     = (const int*)  d_in[3];
    const float* W_self  = (const float*)d_in[4];
    const float* W_sp    = (const float*)d_in[5];
    const float* b_sp    = (const float*)d_in[6];
    const float* W_neigh = (const float*)d_in[7];
    const float* b_neigh = (const float*)d_in[8];
    const float* bias    = (const float*)d_in[9];
    float* out = (float*)d_out;

    void* p_deg = nullptr;
    cudaGetSymbolAddress(&p_deg, g_deg);
    cudaMemsetAsync(p_deg, 0, NN * sizeof(int), 0);

    hist_kernel<<<(EE + 255) / 256, 256>>>(dst);
    part_kernel<<<NPART, 256>>>();
    rowstart_kernel<<<NPART, 256>>>();
    scatter_kernel<<<(EH + 255) / 256, 256>>>(pos, src, dst);
    aggregate_kernel<<<(NN * 2 * 32 + 255) / 256, 256>>>(feat, W_sp, b_sp);
    wprep_kernel<<<(NKC * 8 * 32 + 255) / 256, 256>>>(W_self, W_neigh, b_neigh, bias);
    gemm_kernel<<<(NN + 127) / 128, 256>>>(feat, out);
}

// round 14
// speedup vs baseline: 1.4480x; 1.4480x over previous
#include <cuda_runtime.h>
#include <cuda_bf16.h>
#include <math.h>
#include <stdint.h>

#define NN   50000
#define EE   800000
#define EH   400000   // EE/2
#define INF  64
#define OUTF 64
#define KH   256      // HID*IN
#define KTOT 320      // KH + IN
#define NKC  20       // K chunks of 16
#define NPART 196     // ceil(NN/256)

// ---------------------------------------------------------------------------
// Scratch (__device__ globals)
// ---------------------------------------------------------------------------
__device__ float  g_neigh[(size_t)NN * KH];   // [n][k], mean-scaled
__device__ int    g_deg[NN];
__device__ int    g_rowstart[NN + 1];
__device__ int    g_cursor[NN];
__device__ int    g_part[256];
__device__ float4 g_ws[EE];                   // {wsx, wsy, wsz, bitcast(src)}
__device__ uint4  g_Wfrag[NKC * 8 * 32];      // prepacked B frags {Bh0,Bh1,Bl0,Bl1}
__device__ float  g_bsum[OUTF];               // b_neigh + bias

// ---------------------------------------------------------------------------
// helpers
// ---------------------------------------------------------------------------
#define MMA_BF16(d, a0, a1, a2, a3, b0, b1)                                   \
    asm volatile("mma.sync.aligned.m16n8k16.row.col.f32.bf16.bf16.f32 "       \
                 "{%0,%1,%2,%3}, {%4,%5,%6,%7}, {%8,%9}, {%0,%1,%2,%3};"      \
                 : "+f"((d)[0]), "+f"((d)[1]), "+f"((d)[2]), "+f"((d)[3])     \
                 : "r"(a0), "r"(a1), "r"(a2), "r"(a3), "r"(b0), "r"(b1))

__device__ __forceinline__ uint32_t pk_hi(float2 v, float2& res) {
    __nv_bfloat162 h = __float22bfloat162_rn(v);
    float2 hf = __bfloat1622float2(h);
    res = make_float2(v.x - hf.x, v.y - hf.y);
    return *reinterpret_cast<uint32_t*>(&h);
}
__device__ __forceinline__ uint32_t pk(float2 v) {
    __nv_bfloat162 h = __float22bfloat162_rn(v);
    return *reinterpret_cast<uint32_t*>(&h);
}

// ---------------------------------------------------------------------------
// 1) Degree histogram
// ---------------------------------------------------------------------------
__global__ void hist_kernel(const int* __restrict__ dst)
{
    int e = blockIdx.x * blockDim.x + threadIdx.x;
    if (e < EE) atomicAdd(&g_deg[__ldg(&dst[e])], 1);
}

// ---------------------------------------------------------------------------
// 2a) Per-block degree partial sums
// ---------------------------------------------------------------------------
__global__ void part_kernel()
{
    __shared__ int s[256];
    const int t = threadIdx.x;
    const int idx = blockIdx.x * 256 + t;
    s[t] = (idx < NN) ? g_deg[idx] : 0;
    __syncthreads();
#pragma unroll
    for (int off = 128; off > 0; off >>= 1) {
        if (t < off) s[t] += s[t + off];
        __syncthreads();
    }
    if (t == 0) g_part[blockIdx.x] = s[0];
}

// ---------------------------------------------------------------------------
// 2b) rowstart: each block self-scans the 196 partials, then its 256 degrees
// ---------------------------------------------------------------------------
__global__ void rowstart_kernel()
{
    __shared__ int sp[256];
    __shared__ int s[256];
    const int t = threadIdx.x;

    sp[t] = (t < NPART) ? g_part[t] : 0;
    const int idx = blockIdx.x * 256 + t;
    const int v = (idx < NN) ? g_deg[idx] : 0;
    s[t] = v;
    __syncthreads();
    for (int off = 1; off < 256; off <<= 1) {
        int xp = (t >= off) ? sp[t - off] : 0;
        int x  = (t >= off) ? s[t - off]  : 0;
        __syncthreads();
        sp[t] += xp;
        s[t]  += x;
        __syncthreads();
    }
    const int poff = (blockIdx.x > 0) ? sp[blockIdx.x - 1] : 0;
    const int excl = s[t] - v + poff;
    if (idx < NN) {
        g_rowstart[idx] = excl;
        g_cursor[idx]   = excl;
    }
    if (idx == NN - 1) g_rowstart[NN] = EE;
}

// ---------------------------------------------------------------------------
// 3) Scatter: 2 edges per thread
// ---------------------------------------------------------------------------
__global__ void __launch_bounds__(256) scatter_kernel(
    const float* __restrict__ pos,
    const int*   __restrict__ src,
    const int*   __restrict__ dst)
{
    const int base = blockIdx.x * blockDim.x + threadIdx.x;
    if (base >= EH) return;
#pragma unroll
    for (int h = 0; h < 2; h++) {
        const int e = base + h * EH;
        const int s = __ldg(&src[e]);
        const int d = __ldg(&dst[e]);

        const float rx = __ldg(&pos[d * 3 + 0]) - __ldg(&pos[s * 3 + 0]);
        const float ry = __ldg(&pos[d * 3 + 1]) - __ldg(&pos[s * 3 + 1]);
        const float rz = __ldg(&pos[d * 3 + 2]) - __ldg(&pos[s * 3 + 2]);
        const float scal = sqrtf(fmaf(rx, rx, fmaf(ry, ry, rz * rz))) + 1e-7f;
        const float inv  = __fdividef(1.0f, scal);

        const int p = atomicAdd(&g_cursor[d], 1);
        g_ws[p] = make_float4((rx + 1.0f) * inv, (ry + 1.0f) * inv,
                              (rz + 1.0f) * inv, __int_as_float(s));
    }
}

// ---------------------------------------------------------------------------
// 4) Aggregate: two warps per node; lane owns 4 channels (one `in`).
//    2-edge compute with ONE-iteration-ahead ws prefetch: the feat gather of
//    iteration i depends on ws loaded during iteration i-1, so the per-iter
//    exposed chain is only the feat latency, not ws+feat.
// ---------------------------------------------------------------------------
__global__ void __launch_bounds__(256) aggregate_kernel(
    const float* __restrict__ feat,
    const float* __restrict__ W_sp,
    const float* __restrict__ b_sp)
{
    const int lane = threadIdx.x & 31;
    const int gw   = (blockIdx.x * blockDim.x + threadIdx.x) >> 5;
    const int node = gw >> 1;
    const int half = gw & 1;
    if (node >= NN) return;

    const int k0 = half * 128 + lane * 4;   // 4 channels, same `in`
    const int in = half * 32 + lane;

    float w0[4], w1[4], w2[4], bb[4];
#pragma unroll
    for (int i = 0; i < 4; i++) {
        const int k = k0 + i;
        w0[i] = __ldg(&W_sp[k * 3 + 0]);
        w1[i] = __ldg(&W_sp[k * 3 + 1]);
        w2[i] = __ldg(&W_sp[k * 3 + 2]);
        bb[i] = __ldg(&b_sp[k]);
    }

    const int start = g_rowstart[node];
    const int end   = g_rowstart[node + 1];

    float acc[4], acc2[4];
#pragma unroll
    for (int i = 0; i < 4; i++) { acc[i] = 0.0f; acc2[i] = 0.0f; }

    int j = start;
    float4 wa, wb;
    if (j < end)     wa = __ldg(&g_ws[j]);
    if (j + 1 < end) wb = __ldg(&g_ws[j + 1]);

    for (; j + 2 <= end; j += 2) {
        // gathers depend on ws resolved last iteration (or prologue)
        const float fa = __ldg(&feat[(size_t)__float_as_int(wa.w) * INF + in]);
        const float fb = __ldg(&feat[(size_t)__float_as_int(wb.w) * INF + in]);
        // prefetch next pair (clamped in-bounds; unused values are harmless)
        const int j2 = (j + 2 < end) ? (j + 2) : (end - 1);
        const int j3 = (j + 3 < end) ? (j + 3) : (end - 1);
        const float4 na = __ldg(&g_ws[j2]);
        const float4 nb = __ldg(&g_ws[j3]);
#pragma unroll
        for (int i = 0; i < 4; i++) {
            float ta = fmaf(wa.x, w0[i], fmaf(wa.y, w1[i], fmaf(wa.z, w2[i], bb[i])));
            float tb = fmaf(wb.x, w0[i], fmaf(wb.y, w1[i], fmaf(wb.z, w2[i], bb[i])));
            ta = fmaxf(ta, 0.01f * ta);
            tb = fmaxf(tb, 0.01f * tb);
            acc[i]  = fmaf(ta, fa, acc[i]);
            acc2[i] = fmaf(tb, fb, acc2[i]);
        }
        wa = na;
        wb = nb;
    }
    // remainder (0 or 1 edge): wa already holds ws[end-1]
    if (j < end) {
        const float fa = __ldg(&feat[(size_t)__float_as_int(wa.w) * INF + in]);
#pragma unroll
        for (int i = 0; i < 4; i++) {
            float ta = fmaf(wa.x, w0[i], fmaf(wa.y, w1[i], fmaf(wa.z, w2[i], bb[i])));
            ta = fmaxf(ta, 0.01f * ta);
            acc[i] = fmaf(ta, fa, acc[i]);
        }
    }

    const float sc = (end > start) ? __fdividef(1.0f, (float)(end - start)) : 0.0f;
    *reinterpret_cast<float4*>(&g_neigh[(size_t)node * KH + k0]) =
        make_float4((acc[0] + acc2[0]) * sc, (acc[1] + acc2[1]) * sc,
                    (acc[2] + acc2[2]) * sc, (acc[3] + acc2[3]) * sc);
}

// ---------------------------------------------------------------------------
// 5) Weight prep
// ---------------------------------------------------------------------------
__global__ void wprep_kernel(const float* __restrict__ W_self,
                             const float* __restrict__ W_neigh,
                             const float* __restrict__ b_neigh,
                             const float* __restrict__ bias)
{
    int idx = blockIdx.x * blockDim.x + threadIdx.x;
    if (idx < OUTF) g_bsum[idx] = __ldg(&b_neigh[idx]) + __ldg(&bias[idx]);
    if (idx >= NKC * 8 * 32) return;

    const int lane = idx & 31;
    const int nc   = (idx >> 5) & 7;
    const int kc   = idx >> 8;
    const int n    = nc * 8 + (lane >> 2);
    const int k0   = kc * 16 + (lane & 3) * 2;

    float v[4];
#pragma unroll
    for (int r = 0; r < 2; r++)
#pragma unroll
        for (int j = 0; j < 2; j++) {
            const int k = k0 + r * 8 + j;
            v[r * 2 + j] = (k < KH) ? __ldg(&W_neigh[(size_t)n * KH + k])
                                    : __ldg(&W_self[(size_t)n * INF + (k - KH)]);
        }

    float2 r0, r1;
    uint4 q;
    q.x = pk_hi(make_float2(v[0], v[1]), r0);
    q.y = pk_hi(make_float2(v[2], v[3]), r1);
    q.z = pk(r0);
    q.w = pk(r1);
    g_Wfrag[idx] = q;
}

// ---------------------------------------------------------------------------
// 6) Node GEMM via mma.sync bf16 (3-term hi/lo split), A from f32 gmem.
// ---------------------------------------------------------------------------
__global__ void __launch_bounds__(256) gemm_kernel(
    const float* __restrict__ feat, float* __restrict__ out)
{
    const int lane = threadIdx.x & 31;
    const int warp = threadIdx.x >> 5;
    const int m    = blockIdx.x * 128 + warp * 16 + (lane >> 2);
    const int kq   = (lane & 3) * 2;

    const bool v0 = (m < NN);
    const bool v1 = (m + 8 < NN);
    const float2 z2 = make_float2(0.f, 0.f);

    float D[8][4];
#pragma unroll
    for (int nc = 0; nc < 8; nc++)
#pragma unroll
        for (int i = 0; i < 4; i++) D[nc][i] = 0.0f;

#pragma unroll 4
    for (int kc = 0; kc < NKC; kc++) {
        float2 p00, p10, p01, p11;
        if (kc < 16) {
            const int c = kc * 16 + kq;
            const float* r0 = &g_neigh[(size_t)m * KH + c];
            const float* r1 = &g_neigh[(size_t)(m + 8) * KH + c];
            p00 = v0 ? __ldg(reinterpret_cast<const float2*>(r0))     : z2;
            p01 = v0 ? __ldg(reinterpret_cast<const float2*>(r0 + 8)) : z2;
            p10 = v1 ? __ldg(reinterpret_cast<const float2*>(r1))     : z2;
            p11 = v1 ? __ldg(reinterpret_cast<const float2*>(r1 + 8)) : z2;
        } else {
            const int c = (kc - 16) * 16 + kq;
            const float* r0 = &feat[(size_t)m * INF + c];
            const float* r1 = &feat[(size_t)(m + 8) * INF + c];
            p00 = v0 ? __ldg(reinterpret_cast<const float2*>(r0))     : z2;
            p01 = v0 ? __ldg(reinterpret_cast<const float2*>(r0 + 8)) : z2;
            p10 = v1 ? __ldg(reinterpret_cast<const float2*>(r1))     : z2;
            p11 = v1 ? __ldg(reinterpret_cast<const float2*>(r1 + 8)) : z2;
        }
        float2 q00, q10, q01, q11;
        const uint32_t ah0 = pk_hi(p00, q00);
        const uint32_t ah1 = pk_hi(p10, q10);
        const uint32_t ah2 = pk_hi(p01, q01);
        const uint32_t ah3 = pk_hi(p11, q11);
        const uint32_t al0 = pk(q00), al1 = pk(q10), al2 = pk(q01), al3 = pk(q11);

        const uint4* wf = &g_Wfrag[(kc * 8) * 32 + lane];
#pragma unroll
        for (int nc = 0; nc < 8; nc++) {
            const uint4 b = __ldg(wf + nc * 32);
            MMA_BF16(D[nc], ah0, ah1, ah2, ah3, b.x, b.y);   // Ah * Wh
            MMA_BF16(D[nc], al0, al1, al2, al3, b.x, b.y);   // Al * Wh
            MMA_BF16(D[nc], ah0, ah1, ah2, ah3, b.z, b.w);   // Ah * Wl
        }
    }

#pragma unroll
    for (int nc = 0; nc < 8; nc++) {
        const int n = nc * 8 + kq;
        const float bx = __ldg(&g_bsum[n]);
        const float by = __ldg(&g_bsum[n + 1]);
        if (v0)
            *reinterpret_cast<float2*>(&out[(size_t)m * OUTF + n]) =
                make_float2(D[nc][0] + bx, D[nc][1] + by);
        if (v1)
            *reinterpret_cast<float2*>(&out[(size_t)(m + 8) * OUTF + n]) =
                make_float2(D[nc][2] + bx, D[nc][3] + by);
    }
}

// ---------------------------------------------------------------------------
// Launch
// ---------------------------------------------------------------------------
extern "C" void kernel_launch(void* const* d_in, const int* in_sizes, int n_in,
                              void* d_out, int out_size)
{
    const float* feat    = (const float*)d_in[0];
    const float* pos     = (const float*)d_in[1];
    const int*   src     = (const int*)  d_in[2];
    const int*   dst     = (const int*)  d_in[3];
    const float* W_self  = (const float*)d_in[4];
    const float* W_sp    = (const float*)d_in[5];
    const float* b_sp    = (const float*)d_in[6];
    const float* W_neigh = (const float*)d_in[7];
    const float* b_neigh = (const float*)d_in[8];
    const float* bias    = (const float*)d_in[9];
    float* out = (float*)d_out;

    void* p_deg = nullptr;
    cudaGetSymbolAddress(&p_deg, g_deg);
    cudaMemsetAsync(p_deg, 0, NN * sizeof(int), 0);

    hist_kernel<<<(EE + 255) / 256, 256>>>(dst);
    part_kernel<<<NPART, 256>>>();
    rowstart_kernel<<<NPART, 256>>>();
    scatter_kernel<<<(EH + 255) / 256, 256>>>(pos, src, dst);
    aggregate_kernel<<<(NN * 2 * 32 + 255) / 256, 256>>>(feat, W_sp, b_sp);
    wprep_kernel<<<(NKC * 8 * 32 + 255) / 256, 256>>>(W_self, W_neigh, b_neigh, bias);
    gemm_kernel<<<(NN + 127) / 128, 256>>>(feat, out);
}

// round 15
// speedup vs baseline: 1.4678x; 1.0136x over previous
#include <cuda_runtime.h>
#include <cuda_bf16.h>
#include <math.h>
#include <stdint.h>

#define NN   50000
#define EE   800000
#define EH   400000   // EE/2
#define INF  64
#define OUTF 64
#define KH   256      // HID*IN
#define KTOT 320      // KH + IN
#define NKC  20       // K chunks of 16
#define NPART 196     // ceil(NN/256)

// ---------------------------------------------------------------------------
// Scratch (__device__ globals)
// ---------------------------------------------------------------------------
__device__ float  g_neigh[(size_t)NN * KH];   // [n][k], mean-scaled
__device__ int    g_deg[NN];
__device__ int    g_rowstart[NN + 1];
__device__ int    g_cursor[NN];
__device__ int    g_part[256];
__device__ float4 g_ws[EE];                   // {wsx, wsy, wsz, bitcast(src)}
__device__ uint4  g_Wfrag[NKC * 8 * 32];      // prepacked B frags {Bh0,Bh1,Bl0,Bl1}
__device__ float  g_bsum[OUTF];               // b_neigh + bias

// ---------------------------------------------------------------------------
// helpers
// ---------------------------------------------------------------------------
#define MMA_BF16(d, a0, a1, a2, a3, b0, b1)                                   \
    asm volatile("mma.sync.aligned.m16n8k16.row.col.f32.bf16.bf16.f32 "       \
                 "{%0,%1,%2,%3}, {%4,%5,%6,%7}, {%8,%9}, {%0,%1,%2,%3};"      \
                 : "+f"((d)[0]), "+f"((d)[1]), "+f"((d)[2]), "+f"((d)[3])     \
                 : "r"(a0), "r"(a1), "r"(a2), "r"(a3), "r"(b0), "r"(b1))

__device__ __forceinline__ uint32_t pk_hi(float2 v, float2& res) {
    __nv_bfloat162 h = __float22bfloat162_rn(v);
    float2 hf = __bfloat1622float2(h);
    res = make_float2(v.x - hf.x, v.y - hf.y);
    return *reinterpret_cast<uint32_t*>(&h);
}
__device__ __forceinline__ uint32_t pk(float2 v) {
    __nv_bfloat162 h = __float22bfloat162_rn(v);
    return *reinterpret_cast<uint32_t*>(&h);
}

// ---------------------------------------------------------------------------
// 1) Degree histogram
// ---------------------------------------------------------------------------
__global__ void hist_kernel(const int* __restrict__ dst)
{
    int e = blockIdx.x * blockDim.x + threadIdx.x;
    if (e < EE) atomicAdd(&g_deg[__ldg(&dst[e])], 1);
}

// ---------------------------------------------------------------------------
// 2a) Per-block degree partial sums
// ---------------------------------------------------------------------------
__global__ void part_kernel()
{
    __shared__ int s[256];
    const int t = threadIdx.x;
    const int idx = blockIdx.x * 256 + t;
    s[t] = (idx < NN) ? g_deg[idx] : 0;
    __syncthreads();
#pragma unroll
    for (int off = 128; off > 0; off >>= 1) {
        if (t < off) s[t] += s[t + off];
        __syncthreads();
    }
    if (t == 0) g_part[blockIdx.x] = s[0];
}

// ---------------------------------------------------------------------------
// 2b) rowstart: each block self-scans the 196 partials, then its 256 degrees
// ---------------------------------------------------------------------------
__global__ void rowstart_kernel()
{
    __shared__ int sp[256];
    __shared__ int s[256];
    const int t = threadIdx.x;

    sp[t] = (t < NPART) ? g_part[t] : 0;
    const int idx = blockIdx.x * 256 + t;
    const int v = (idx < NN) ? g_deg[idx] : 0;
    s[t] = v;
    __syncthreads();
    for (int off = 1; off < 256; off <<= 1) {
        int xp = (t >= off) ? sp[t - off] : 0;
        int x  = (t >= off) ? s[t - off]  : 0;
        __syncthreads();
        sp[t] += xp;
        s[t]  += x;
        __syncthreads();
    }
    const int poff = (blockIdx.x > 0) ? sp[blockIdx.x - 1] : 0;
    const int excl = s[t] - v + poff;
    if (idx < NN) {
        g_rowstart[idx] = excl;
        g_cursor[idx]   = excl;
    }
    if (idx == NN - 1) g_rowstart[NN] = EE;
}

// ---------------------------------------------------------------------------
// 3) Scatter: 2 edges per thread
// ---------------------------------------------------------------------------
__global__ void __launch_bounds__(256) scatter_kernel(
    const float* __restrict__ pos,
    const int*   __restrict__ src,
    const int*   __restrict__ dst)
{
    const int base = blockIdx.x * blockDim.x + threadIdx.x;
    if (base >= EH) return;
#pragma unroll
    for (int h = 0; h < 2; h++) {
        const int e = base + h * EH;
        const int s = __ldg(&src[e]);
        const int d = __ldg(&dst[e]);

        const float rx = __ldg(&pos[d * 3 + 0]) - __ldg(&pos[s * 3 + 0]);
        const float ry = __ldg(&pos[d * 3 + 1]) - __ldg(&pos[s * 3 + 1]);
        const float rz = __ldg(&pos[d * 3 + 2]) - __ldg(&pos[s * 3 + 2]);
        const float scal = sqrtf(fmaf(rx, rx, fmaf(ry, ry, rz * rz))) + 1e-7f;
        const float inv  = __fdividef(1.0f, scal);

        const int p = atomicAdd(&g_cursor[d], 1);
        g_ws[p] = make_float4((rx + 1.0f) * inv, (ry + 1.0f) * inv,
                              (rz + 1.0f) * inv, __int_as_float(s));
    }
}

// ---------------------------------------------------------------------------
// 4) Aggregate: two warps per node; lane owns 4 channels (one `in`), 2-edge
//    unroll, dual accumulator banks. Leaky via prescaled weights + one
//    abs-operand FFMA:  t' = ws·(0.505W)+0.505b;  leaky = t' + R·|t'|,
//    R = 0.495/0.505. Saves FMUL+FMNMX per channel per edge.
// ---------------------------------------------------------------------------
__global__ void __launch_bounds__(256, 5) aggregate_kernel(
    const float* __restrict__ feat,
    const float* __restrict__ W_sp,
    const float* __restrict__ b_sp)
{
    const int lane = threadIdx.x & 31;
    const int gw   = (blockIdx.x * blockDim.x + threadIdx.x) >> 5;
    const int node = gw >> 1;
    const int half = gw & 1;
    if (node >= NN) return;

    const int k0 = half * 128 + lane * 4;   // 4 channels, same `in`
    const int in = half * 32 + lane;
    const float R = 0.495f / 0.505f;

    float w0[4], w1[4], w2[4], bb[4];
#pragma unroll
    for (int i = 0; i < 4; i++) {
        const int k = k0 + i;
        w0[i] = 0.505f * __ldg(&W_sp[k * 3 + 0]);
        w1[i] = 0.505f * __ldg(&W_sp[k * 3 + 1]);
        w2[i] = 0.505f * __ldg(&W_sp[k * 3 + 2]);
        bb[i] = 0.505f * __ldg(&b_sp[k]);
    }

    const int start = g_rowstart[node];
    const int end   = g_rowstart[node + 1];

    float acc[4], acc2[4];
#pragma unroll
    for (int i = 0; i < 4; i++) { acc[i] = 0.0f; acc2[i] = 0.0f; }

    int j = start;
    for (; j + 2 <= end; j += 2) {
        const float4 wa = __ldg(&g_ws[j]);
        const float4 wb = __ldg(&g_ws[j + 1]);
        const float fa = __ldg(&feat[(size_t)__float_as_int(wa.w) * INF + in]);
        const float fb = __ldg(&feat[(size_t)__float_as_int(wb.w) * INF + in]);
#pragma unroll
        for (int i = 0; i < 4; i++) {
            float ta = fmaf(wa.x, w0[i], fmaf(wa.y, w1[i], fmaf(wa.z, w2[i], bb[i])));
            float tb = fmaf(wb.x, w0[i], fmaf(wb.y, w1[i], fmaf(wb.z, w2[i], bb[i])));
            ta = fmaf(fabsf(ta), R, ta);    // leaky (abs folds into FFMA)
            tb = fmaf(fabsf(tb), R, tb);
            acc[i]  = fmaf(ta, fa, acc[i]);
            acc2[i] = fmaf(tb, fb, acc2[i]);
        }
    }
    if (j < end) {
        const float4 wa = __ldg(&g_ws[j]);
        const float fa = __ldg(&feat[(size_t)__float_as_int(wa.w) * INF + in]);
#pragma unroll
        for (int i = 0; i < 4; i++) {
            float ta = fmaf(wa.x, w0[i], fmaf(wa.y, w1[i], fmaf(wa.z, w2[i], bb[i])));
            ta = fmaf(fabsf(ta), R, ta);
            acc[i] = fmaf(ta, fa, acc[i]);
        }
    }

    const float sc = (end > start) ? __fdividef(1.0f, (float)(end - start)) : 0.0f;
    *reinterpret_cast<float4*>(&g_neigh[(size_t)node * KH + k0]) =
        make_float4((acc[0] + acc2[0]) * sc, (acc[1] + acc2[1]) * sc,
                    (acc[2] + acc2[2]) * sc, (acc[3] + acc2[3]) * sc);
}

// ---------------------------------------------------------------------------
// 5) Weight prep
// ---------------------------------------------------------------------------
__global__ void wprep_kernel(const float* __restrict__ W_self,
                             const float* __restrict__ W_neigh,
                             const float* __restrict__ b_neigh,
                             const float* __restrict__ bias)
{
    int idx = blockIdx.x * blockDim.x + threadIdx.x;
    if (idx < OUTF) g_bsum[idx] = __ldg(&b_neigh[idx]) + __ldg(&bias[idx]);
    if (idx >= NKC * 8 * 32) return;

    const int lane = idx & 31;
    const int nc   = (idx >> 5) & 7;
    const int kc   = idx >> 8;
    const int n    = nc * 8 + (lane >> 2);
    const int k0   = kc * 16 + (lane & 3) * 2;

    float v[4];
#pragma unroll
    for (int r = 0; r < 2; r++)
#pragma unroll
        for (int j = 0; j < 2; j++) {
            const int k = k0 + r * 8 + j;
            v[r * 2 + j] = (k < KH) ? __ldg(&W_neigh[(size_t)n * KH + k])
                                    : __ldg(&W_self[(size_t)n * INF + (k - KH)]);
        }

    float2 r0, r1;
    uint4 q;
    q.x = pk_hi(make_float2(v[0], v[1]), r0);
    q.y = pk_hi(make_float2(v[2], v[3]), r1);
    q.z = pk(r0);
    q.w = pk(r1);
    g_Wfrag[idx] = q;
}

// ---------------------------------------------------------------------------
// 6) Node GEMM via mma.sync bf16 (3-term hi/lo split), A from f32 gmem.
// ---------------------------------------------------------------------------
__global__ void __launch_bounds__(256) gemm_kernel(
    const float* __restrict__ feat, float* __restrict__ out)
{
    const int lane = threadIdx.x & 31;
    const int warp = threadIdx.x >> 5;
    const int m    = blockIdx.x * 128 + warp * 16 + (lane >> 2);
    const int kq   = (lane & 3) * 2;

    const bool v0 = (m < NN);
    const bool v1 = (m + 8 < NN);
    const float2 z2 = make_float2(0.f, 0.f);

    float D[8][4];
#pragma unroll
    for (int nc = 0; nc < 8; nc++)
#pragma unroll
        for (int i = 0; i < 4; i++) D[nc][i] = 0.0f;

#pragma unroll 4
    for (int kc = 0; kc < NKC; kc++) {
        float2 p00, p10, p01, p11;
        if (kc < 16) {
            const int c = kc * 16 + kq;
            const float* r0 = &g_neigh[(size_t)m * KH + c];
            const float* r1 = &g_neigh[(size_t)(m + 8) * KH + c];
            p00 = v0 ? __ldg(reinterpret_cast<const float2*>(r0))     : z2;
            p01 = v0 ? __ldg(reinterpret_cast<const float2*>(r0 + 8)) : z2;
            p10 = v1 ? __ldg(reinterpret_cast<const float2*>(r1))     : z2;
            p11 = v1 ? __ldg(reinterpret_cast<const float2*>(r1 + 8)) : z2;
        } else {
            const int c = (kc - 16) * 16 + kq;
            const float* r0 = &feat[(size_t)m * INF + c];
            const float* r1 = &feat[(size_t)(m + 8) * INF + c];
            p00 = v0 ? __ldg(reinterpret_cast<const float2*>(r0))     : z2;
            p01 = v0 ? __ldg(reinterpret_cast<const float2*>(r0 + 8)) : z2;
            p10 = v1 ? __ldg(reinterpret_cast<const float2*>(r1))     : z2;
            p11 = v1 ? __ldg(reinterpret_cast<const float2*>(r1 + 8)) : z2;
        }
        float2 q00, q10, q01, q11;
        const uint32_t ah0 = pk_hi(p00, q00);
        const uint32_t ah1 = pk_hi(p10, q10);
        const uint32_t ah2 = pk_hi(p01, q01);
        const uint32_t ah3 = pk_hi(p11, q11);
        const uint32_t al0 = pk(q00), al1 = pk(q10), al2 = pk(q01), al3 = pk(q11);

        const uint4* wf = &g_Wfrag[(kc * 8) * 32 + lane];
#pragma unroll
        for (int nc = 0; nc < 8; nc++) {
            const uint4 b = __ldg(wf + nc * 32);
            MMA_BF16(D[nc], ah0, ah1, ah2, ah3, b.x, b.y);   // Ah * Wh
            MMA_BF16(D[nc], al0, al1, al2, al3, b.x, b.y);   // Al * Wh
            MMA_BF16(D[nc], ah0, ah1, ah2, ah3, b.z, b.w);   // Ah * Wl
        }
    }

#pragma unroll
    for (int nc = 0; nc < 8; nc++) {
        const int n = nc * 8 + kq;
        const float bx = __ldg(&g_bsum[n]);
        const float by = __ldg(&g_bsum[n + 1]);
        if (v0)
            *reinterpret_cast<float2*>(&out[(size_t)m * OUTF + n]) =
                make_float2(D[nc][0] + bx, D[nc][1] + by);
        if (v1)
            *reinterpret_cast<float2*>(&out[(size_t)(m + 8) * OUTF + n]) =
                make_float2(D[nc][2] + bx, D[nc][3] + by);
    }
}

// ---------------------------------------------------------------------------
// Launch
// ---------------------------------------------------------------------------
extern "C" void kernel_launch(void* const* d_in, const int* in_sizes, int n_in,
                              void* d_out, int out_size)
{
    const float* feat    = (const float*)d_in[0];
    const float* pos     = (const float*)d_in[1];
    const int*   src     = (const int*)  d_in[2];
    const int*   dst     = (const int*)  d_in[3];
    const float* W_self  = (const float*)d_in[4];
    const float* W_sp    = (const float*)d_in[5];
    const float* b_sp    = (const float*)d_in[6];
    const float* W_neigh = (const float*)d_in[7];
    const float* b_neigh = (const float*)d_in[8];
    const float* bias    = (const float*)d_in[9];
    float* out = (float*)d_out;

    void* p_deg = nullptr;
    cudaGetSymbolAddress(&p_deg, g_deg);
    cudaMemsetAsync(p_deg, 0, NN * sizeof(int), 0);

    hist_kernel<<<(EE + 255) / 256, 256>>>(dst);
    part_kernel<<<NPART, 256>>>();
    rowstart_kernel<<<NPART, 256>>>();
    scatter_kernel<<<(EH + 255) / 256, 256>>>(pos, src, dst);
    aggregate_kernel<<<(NN * 2 * 32 + 255) / 256, 256>>>(feat, W_sp, b_sp);
    wprep_kernel<<<(NKC * 8 * 32 + 255) / 256, 256>>>(W_self, W_neigh, b_neigh, bias);
    gemm_kernel<<<(NN + 127) / 128, 256>>>(feat, out);
}

// round 16
// speedup vs baseline: 1.4884x; 1.0140x over previous
#include <cuda_runtime.h>
#include <cuda_bf16.h>
#include <math.h>
#include <stdint.h>

#define NN   50000
#define EE   800000
#define EH   400000   // EE/2
#define INF  64
#define OUTF 64
#define KH   256      // HID*IN
#define KTOT 320      // KH + IN
#define NKC  20       // K chunks of 16
#define NPART 196     // ceil(NN/256)

// ---------------------------------------------------------------------------
// Scratch (__device__ globals)
// ---------------------------------------------------------------------------
__device__ float  g_neigh[(size_t)NN * KH];   // [n][k], mean-scaled
__device__ int    g_deg[NN];
__device__ int    g_rowstart[NN + 1];
__device__ int    g_cursor[NN];
__device__ int    g_part[256];
__device__ float4 g_ws[EE];                   // {wsx, wsy, wsz, bitcast(src)}
__device__ uint4  g_Wfrag[NKC * 8 * 32];      // prepacked B frags {Bh0,Bh1,Bl0,Bl1}
__device__ float  g_bsum[OUTF];               // b_neigh + bias

// ---------------------------------------------------------------------------
// helpers
// ---------------------------------------------------------------------------
#define MMA_BF16(d, a0, a1, a2, a3, b0, b1)                                   \
    asm volatile("mma.sync.aligned.m16n8k16.row.col.f32.bf16.bf16.f32 "       \
                 "{%0,%1,%2,%3}, {%4,%5,%6,%7}, {%8,%9}, {%0,%1,%2,%3};"      \
                 : "+f"((d)[0]), "+f"((d)[1]), "+f"((d)[2]), "+f"((d)[3])     \
                 : "r"(a0), "r"(a1), "r"(a2), "r"(a3), "r"(b0), "r"(b1))

__device__ __forceinline__ uint32_t pk_hi(float2 v, float2& res) {
    __nv_bfloat162 h = __float22bfloat162_rn(v);
    float2 hf = __bfloat1622float2(h);
    res = make_float2(v.x - hf.x, v.y - hf.y);
    return *reinterpret_cast<uint32_t*>(&h);
}
__device__ __forceinline__ uint32_t pk(float2 v) {
    __nv_bfloat162 h = __float22bfloat162_rn(v);
    return *reinterpret_cast<uint32_t*>(&h);
}

// ---------------------------------------------------------------------------
// 1) Degree histogram
// ---------------------------------------------------------------------------
__global__ void hist_kernel(const int* __restrict__ dst)
{
    int e = blockIdx.x * blockDim.x + threadIdx.x;
    if (e < EE) atomicAdd(&g_deg[__ldg(&dst[e])], 1);
}

// ---------------------------------------------------------------------------
// 2a) Per-block degree partial sums
// ---------------------------------------------------------------------------
__global__ void part_kernel()
{
    __shared__ int s[256];
    const int t = threadIdx.x;
    const int idx = blockIdx.x * 256 + t;
    s[t] = (idx < NN) ? g_deg[idx] : 0;
    __syncthreads();
#pragma unroll
    for (int off = 128; off > 0; off >>= 1) {
        if (t < off) s[t] += s[t + off];
        __syncthreads();
    }
    if (t == 0) g_part[blockIdx.x] = s[0];
}

// ---------------------------------------------------------------------------
// 2b) rowstart: each block self-scans the 196 partials, then its 256 degrees
// ---------------------------------------------------------------------------
__global__ void rowstart_kernel()
{
    __shared__ int sp[256];
    __shared__ int s[256];
    const int t = threadIdx.x;

    sp[t] = (t < NPART) ? g_part[t] : 0;
    const int idx = blockIdx.x * 256 + t;
    const int v = (idx < NN) ? g_deg[idx] : 0;
    s[t] = v;
    __syncthreads();
    for (int off = 1; off < 256; off <<= 1) {
        int xp = (t >= off) ? sp[t - off] : 0;
        int x  = (t >= off) ? s[t - off]  : 0;
        __syncthreads();
        sp[t] += xp;
        s[t]  += x;
        __syncthreads();
    }
    const int poff = (blockIdx.x > 0) ? sp[blockIdx.x - 1] : 0;
    const int excl = s[t] - v + poff;
    if (idx < NN) {
        g_rowstart[idx] = excl;
        g_cursor[idx]   = excl;
    }
    if (idx == NN - 1) g_rowstart[NN] = EE;
}

// ---------------------------------------------------------------------------
// 3) Scatter: 2 edges per thread
// ---------------------------------------------------------------------------
__global__ void __launch_bounds__(256) scatter_kernel(
    const float* __restrict__ pos,
    const int*   __restrict__ src,
    const int*   __restrict__ dst)
{
    const int base = blockIdx.x * blockDim.x + threadIdx.x;
    if (base >= EH) return;
#pragma unroll
    for (int h = 0; h < 2; h++) {
        const int e = base + h * EH;
        const int s = __ldg(&src[e]);
        const int d = __ldg(&dst[e]);

        const float rx = __ldg(&pos[d * 3 + 0]) - __ldg(&pos[s * 3 + 0]);
        const float ry = __ldg(&pos[d * 3 + 1]) - __ldg(&pos[s * 3 + 1]);
        const float rz = __ldg(&pos[d * 3 + 2]) - __ldg(&pos[s * 3 + 2]);
        const float scal = sqrtf(fmaf(rx, rx, fmaf(ry, ry, rz * rz))) + 1e-7f;
        const float inv  = __fdividef(1.0f, scal);

        const int p = atomicAdd(&g_cursor[d], 1);
        g_ws[p] = make_float4((rx + 1.0f) * inv, (ry + 1.0f) * inv,
                              (rz + 1.0f) * inv, __int_as_float(s));
    }
}

// ---------------------------------------------------------------------------
// 4) Aggregate: two warps per node; lane owns 4 channels (one `in`), 2-edge
//    compute, dual acc banks, leaky via prescaled abs-FFMA. TWO-stage software
//    pipeline: ws held 2 iterations ahead so the feat gather for iteration
//    i+1 issues in iteration i with no intra-iteration dependency.
// ---------------------------------------------------------------------------
__global__ void __launch_bounds__(256, 4) aggregate_kernel(
    const float* __restrict__ feat,
    const float* __restrict__ W_sp,
    const float* __restrict__ b_sp)
{
    const int lane = threadIdx.x & 31;
    const int gw   = (blockIdx.x * blockDim.x + threadIdx.x) >> 5;
    const int node = gw >> 1;
    const int half = gw & 1;
    if (node >= NN) return;

    const int k0 = half * 128 + lane * 4;   // 4 channels, same `in`
    const int in = half * 32 + lane;
    const float R = 0.495f / 0.505f;
    const float* __restrict__ fp = feat + in;

    float w0[4], w1[4], w2[4], bb[4];
#pragma unroll
    for (int i = 0; i < 4; i++) {
        const int k = k0 + i;
        w0[i] = 0.505f * __ldg(&W_sp[k * 3 + 0]);
        w1[i] = 0.505f * __ldg(&W_sp[k * 3 + 1]);
        w2[i] = 0.505f * __ldg(&W_sp[k * 3 + 2]);
        bb[i] = 0.505f * __ldg(&b_sp[k]);
    }

    const int start = g_rowstart[node];
    const int end   = g_rowstart[node + 1];

    float acc[4], acc2[4];
#pragma unroll
    for (int i = 0; i < 4; i++) { acc[i] = 0.0f; acc2[i] = 0.0f; }

    if (start < end) {
        const int last = end - 1;
        // Prologue: ws for iters 0 and 1 (clamped), feat for iter 0.
        int j = start;
        float4 wa  = __ldg(&g_ws[j]);
        float4 wb  = __ldg(&g_ws[min(j + 1, last)]);
        float4 wa2 = __ldg(&g_ws[min(j + 2, last)]);
        float4 wb2 = __ldg(&g_ws[min(j + 3, last)]);
        float  fa  = __ldg(fp + ((size_t)(uint32_t)__float_as_int(wa.w) << 6));
        float  fb  = __ldg(fp + ((size_t)(uint32_t)__float_as_int(wb.w) << 6));

        for (; j + 2 <= end; j += 2) {
            // feat for next iteration: depends only on wa2/wb2 (resolved)
            const float fa2 = __ldg(fp + ((size_t)(uint32_t)__float_as_int(wa2.w) << 6));
            const float fb2 = __ldg(fp + ((size_t)(uint32_t)__float_as_int(wb2.w) << 6));
            // ws two iterations ahead (clamped)
            const float4 wa3 = __ldg(&g_ws[min(j + 4, last)]);
            const float4 wb3 = __ldg(&g_ws[min(j + 5, last)]);
#pragma unroll
            for (int i = 0; i < 4; i++) {
                float ta = fmaf(wa.x, w0[i], fmaf(wa.y, w1[i], fmaf(wa.z, w2[i], bb[i])));
                float tb = fmaf(wb.x, w0[i], fmaf(wb.y, w1[i], fmaf(wb.z, w2[i], bb[i])));
                ta = fmaf(fabsf(ta), R, ta);
                tb = fmaf(fabsf(tb), R, tb);
                acc[i]  = fmaf(ta, fa, acc[i]);
                acc2[i] = fmaf(tb, fb, acc2[i]);
            }
            wa = wa2; wb = wb2; wa2 = wa3; wb2 = wb3;
            fa = fa2; fb = fb2;
        }
        // remainder (0 or 1 edge): wa/fa hold ws[end-1]/feat(end-1) via shifts
        if (j < end) {
#pragma unroll
            for (int i = 0; i < 4; i++) {
                float ta = fmaf(wa.x, w0[i], fmaf(wa.y, w1[i], fmaf(wa.z, w2[i], bb[i])));
                ta = fmaf(fabsf(ta), R, ta);
                acc[i] = fmaf(ta, fa, acc[i]);
            }
        }
    }

    const float sc = (end > start) ? __fdividef(1.0f, (float)(end - start)) : 0.0f;
    *reinterpret_cast<float4*>(&g_neigh[(size_t)node * KH + k0]) =
        make_float4((acc[0] + acc2[0]) * sc, (acc[1] + acc2[1]) * sc,
                    (acc[2] + acc2[2]) * sc, (acc[3] + acc2[3]) * sc);
}

// ---------------------------------------------------------------------------
// 5) Weight prep
// ---------------------------------------------------------------------------
__global__ void wprep_kernel(const float* __restrict__ W_self,
                             const float* __restrict__ W_neigh,
                             const float* __restrict__ b_neigh,
                             const float* __restrict__ bias)
{
    int idx = blockIdx.x * blockDim.x + threadIdx.x;
    if (idx < OUTF) g_bsum[idx] = __ldg(&b_neigh[idx]) + __ldg(&bias[idx]);
    if (idx >= NKC * 8 * 32) return;

    const int lane = idx & 31;
    const int nc   = (idx >> 5) & 7;
    const int kc   = idx >> 8;
    const int n    = nc * 8 + (lane >> 2);
    const int k0   = kc * 16 + (lane & 3) * 2;

    float v[4];
#pragma unroll
    for (int r = 0; r < 2; r++)
#pragma unroll
        for (int j = 0; j < 2; j++) {
            const int k = k0 + r * 8 + j;
            v[r * 2 + j] = (k < KH) ? __ldg(&W_neigh[(size_t)n * KH + k])
                                    : __ldg(&W_self[(size_t)n * INF + (k - KH)]);
        }

    float2 r0, r1;
    uint4 q;
    q.x = pk_hi(make_float2(v[0], v[1]), r0);
    q.y = pk_hi(make_float2(v[2], v[3]), r1);
    q.z = pk(r0);
    q.w = pk(r1);
    g_Wfrag[idx] = q;
}

// ---------------------------------------------------------------------------
// 6) Node GEMM via mma.sync bf16 (3-term hi/lo split), A from f32 gmem.
// ---------------------------------------------------------------------------
__global__ void __launch_bounds__(256) gemm_kernel(
    const float* __restrict__ feat, float* __restrict__ out)
{
    const int lane = threadIdx.x & 31;
    const int warp = threadIdx.x >> 5;
    const int m    = blockIdx.x * 128 + warp * 16 + (lane >> 2);
    const int kq   = (lane & 3) * 2;

    const bool v0 = (m < NN);
    const bool v1 = (m + 8 < NN);
    const float2 z2 = make_float2(0.f, 0.f);

    float D[8][4];
#pragma unroll
    for (int nc = 0; nc < 8; nc++)
#pragma unroll
        for (int i = 0; i < 4; i++) D[nc][i] = 0.0f;

#pragma unroll 4
    for (int kc = 0; kc < NKC; kc++) {
        float2 p00, p10, p01, p11;
        if (kc < 16) {
            const int c = kc * 16 + kq;
            const float* r0 = &g_neigh[(size_t)m * KH + c];
            const float* r1 = &g_neigh[(size_t)(m + 8) * KH + c];
            p00 = v0 ? __ldg(reinterpret_cast<const float2*>(r0))     : z2;
            p01 = v0 ? __ldg(reinterpret_cast<const float2*>(r0 + 8)) : z2;
            p10 = v1 ? __ldg(reinterpret_cast<const float2*>(r1))     : z2;
            p11 = v1 ? __ldg(reinterpret_cast<const float2*>(r1 + 8)) : z2;
        } else {
            const int c = (kc - 16) * 16 + kq;
            const float* r0 = &feat[(size_t)m * INF + c];
            const float* r1 = &feat[(size_t)(m + 8) * INF + c];
            p00 = v0 ? __ldg(reinterpret_cast<const float2*>(r0))     : z2;
            p01 = v0 ? __ldg(reinterpret_cast<const float2*>(r0 + 8)) : z2;
            p10 = v1 ? __ldg(reinterpret_cast<const float2*>(r1))     : z2;
            p11 = v1 ? __ldg(reinterpret_cast<const float2*>(r1 + 8)) : z2;
        }
        float2 q00, q10, q01, q11;
        const uint32_t ah0 = pk_hi(p00, q00);
        const uint32_t ah1 = pk_hi(p10, q10);
        const uint32_t ah2 = pk_hi(p01, q01);
        const uint32_t ah3 = pk_hi(p11, q11);
        const uint32_t al0 = pk(q00), al1 = pk(q10), al2 = pk(q01), al3 = pk(q11);

        const uint4* wf = &g_Wfrag[(kc * 8) * 32 + lane];
#pragma unroll
        for (int nc = 0; nc < 8; nc++) {
            const uint4 b = __ldg(wf + nc * 32);
            MMA_BF16(D[nc], ah0, ah1, ah2, ah3, b.x, b.y);   // Ah * Wh
            MMA_BF16(D[nc], al0, al1, al2, al3, b.x, b.y);   // Al * Wh
            MMA_BF16(D[nc], ah0, ah1, ah2, ah3, b.z, b.w);   // Ah * Wl
        }
    }

#pragma unroll
    for (int nc = 0; nc < 8; nc++) {
        const int n = nc * 8 + kq;
        const float bx = __ldg(&g_bsum[n]);
        const float by = __ldg(&g_bsum[n + 1]);
        if (v0)
            *reinterpret_cast<float2*>(&out[(size_t)m * OUTF + n]) =
                make_float2(D[nc][0] + bx, D[nc][1] + by);
        if (v1)
            *reinterpret_cast<float2*>(&out[(size_t)(m + 8) * OUTF + n]) =
                make_float2(D[nc][2] + bx, D[nc][3] + by);
    }
}

// ---------------------------------------------------------------------------
// Launch
// ---------------------------------------------------------------------------
extern "C" void kernel_launch(void* const* d_in, const int* in_sizes, int n_in,
                              void* d_out, int out_size)
{
    const float* feat    = (const float*)d_in[0];
    const float* pos     = (const float*)d_in[1];
    const int*   src     = (const int*)  d_in[2];
    const int*   dst     = (const int*)  d_in[3];
    const float* W_self  = (const float*)d_in[4];
    const float* W_sp    = (const float*)d_in[5];
    const float* b_sp    = (const float*)d_in[6];
    const float* W_neigh = (const float*)d_in[7];
    const float* b_neigh = (const float*)d_in[8];
    const float* bias    = (const float*)d_in[9];
    float* out = (float*)d_out;

    void* p_deg = nullptr;
    cudaGetSymbolAddress(&p_deg, g_deg);
    cudaMemsetAsync(p_deg, 0, NN * sizeof(int), 0);

    hist_kernel<<<(EE + 255) / 256, 256>>>(dst);
    part_kernel<<<NPART, 256>>>();
    rowstart_kernel<<<NPART, 256>>>();
    scatter_kernel<<<(EH + 255) / 256, 256>>>(pos, src, dst);
    aggregate_kernel<<<(NN * 2 * 32 + 255) / 256, 256>>>(feat, W_sp, b_sp);
    wprep_kernel<<<(NKC * 8 * 32 + 255) / 256, 256>>>(W_self, W_neigh, b_neigh, bias);
    gemm_kernel<<<(NN + 127) / 128, 256>>>(feat, out);
}